// round 8
// baseline (speedup 1.0000x reference)
#include <cuda_runtime.h>
#include <math.h>

#define NN 100000
#define EE 3200000
#define FEAT 128
#define HID 16
#define NC 20
#define CAP 128            // padded CSR slots per node
#define ROWF 16            // 64B row

// ---- device scratch ----
__device__ __align__(128) float g_bufA[NN * ROWF];
__device__ __align__(128) float g_bufB[NN * ROWF];
__device__ float g_rA[NN];
__device__ float g_rB[NN];
__device__ int   g_counts[NN];      // BSS-zeroed; re-zeroed by prop2 each launch
__device__ int   g_csr[NN * CAP];

__device__ __forceinline__ float dot4(float4 a, float4 b) {
    return a.x * b.x + a.y * b.y + a.z * b.z + a.w * b.w;
}

// ---------------- fused front: interleaved CSR-scatter + gemm1 blocks ----------------
// trio layout: bid%3==2 -> scatter block (scat_id=bid/3), else gemm (gemm_id=(bid/3)*2+rem)
__global__ void __launch_bounds__(256) k_front(
    const int* __restrict__ ids, const float* __restrict__ emb,
    const float* __restrict__ W1, const float* __restrict__ b1,
    const int* __restrict__ src, const int* __restrict__ dst,
    int n, int E, int trios, int gemm_blks) {

    int bid = blockIdx.x;
    int rem = bid % 3;

    if (rem == 2) {
        // ---- scatter: 16 edges / iteration, MLP-16 atomics ----
        int tid = (bid / 3) * 256 + threadIdx.x;
        int stride = trios * 256;
        const int4* src4 = (const int4*)src;
        const int4* dst4 = (const int4*)dst;
        int E16 = E >> 4;
        for (int i = tid; i < E16; i += stride) {
            int4 d0 = __ldg(dst4 + 4 * i + 0);
            int4 d1 = __ldg(dst4 + 4 * i + 1);
            int4 d2 = __ldg(dst4 + 4 * i + 2);
            int4 d3 = __ldg(dst4 + 4 * i + 3);
            int4 s0 = __ldg(src4 + 4 * i + 0);
            int4 s1 = __ldg(src4 + 4 * i + 1);
            int4 s2 = __ldg(src4 + 4 * i + 2);
            int4 s3 = __ldg(src4 + 4 * i + 3);
            int p0  = atomicAdd(&g_counts[d0.x], 1);
            int p1  = atomicAdd(&g_counts[d0.y], 1);
            int p2  = atomicAdd(&g_counts[d0.z], 1);
            int p3  = atomicAdd(&g_counts[d0.w], 1);
            int p4  = atomicAdd(&g_counts[d1.x], 1);
            int p5  = atomicAdd(&g_counts[d1.y], 1);
            int p6  = atomicAdd(&g_counts[d1.z], 1);
            int p7  = atomicAdd(&g_counts[d1.w], 1);
            int p8  = atomicAdd(&g_counts[d2.x], 1);
            int p9  = atomicAdd(&g_counts[d2.y], 1);
            int p10 = atomicAdd(&g_counts[d2.z], 1);
            int p11 = atomicAdd(&g_counts[d2.w], 1);
            int p12 = atomicAdd(&g_counts[d3.x], 1);
            int p13 = atomicAdd(&g_counts[d3.y], 1);
            int p14 = atomicAdd(&g_counts[d3.z], 1);
            int p15 = atomicAdd(&g_counts[d3.w], 1);
            if (p0  < CAP) g_csr[d0.x * CAP + p0 ] = s0.x;
            if (p1  < CAP) g_csr[d0.y * CAP + p1 ] = s0.y;
            if (p2  < CAP) g_csr[d0.z * CAP + p2 ] = s0.z;
            if (p3  < CAP) g_csr[d0.w * CAP + p3 ] = s0.w;
            if (p4  < CAP) g_csr[d1.x * CAP + p4 ] = s1.x;
            if (p5  < CAP) g_csr[d1.y * CAP + p5 ] = s1.y;
            if (p6  < CAP) g_csr[d1.z * CAP + p6 ] = s1.z;
            if (p7  < CAP) g_csr[d1.w * CAP + p7 ] = s1.w;
            if (p8  < CAP) g_csr[d2.x * CAP + p8 ] = s2.x;
            if (p9  < CAP) g_csr[d2.y * CAP + p9 ] = s2.y;
            if (p10 < CAP) g_csr[d2.z * CAP + p10] = s2.z;
            if (p11 < CAP) g_csr[d2.w * CAP + p11] = s2.w;
            if (p12 < CAP) g_csr[d3.x * CAP + p12] = s3.x;
            if (p13 < CAP) g_csr[d3.y * CAP + p13] = s3.y;
            if (p14 < CAP) g_csr[d3.z * CAP + p14] = s3.z;
            if (p15 < CAP) g_csr[d3.w * CAP + p15] = s3.w;
        }
        for (int i = (E16 << 4) + tid; i < E; i += stride) {
            int d = __ldg(dst + i);
            int p = atomicAdd(&g_counts[d], 1);
            if (p < CAP) g_csr[d * CAP + p] = __ldg(src + i);
        }
        return;
    }

    // ---- gemm1: 64 nodes/block, 4 nodes/thread ----
    int gemm_id = (bid / 3) * 2 + rem;
    if (gemm_id >= gemm_blks) return;

    __shared__ float w1t[16 * 132];
    __shared__ float sx[64][132];

    int t = threadIdx.x;
    for (int idx = t; idx < FEAT * HID; idx += 256) {
        int k = idx >> 4, j = idx & 15;
        w1t[j * 132 + k] = W1[idx];
    }

    int base = gemm_id * 64;
    int warp = t >> 5, lane = t & 31;

    for (int rr = warp; rr < 64; rr += 8) {
        int node = base + rr;
        int id = (node < n) ? __ldg(ids + node) : 0;
        float4 v = __ldg(((const float4*)(emb + (size_t)id * FEAT)) + lane);
        ((float4*)&sx[rr][0])[lane] = v;
    }
    __syncthreads();

    int j = t & 15, g = t >> 4;
    const float4* wr = (const float4*)(w1t + j * 132);
    const float4* x0 = (const float4*)&sx[g * 4 + 0][0];
    const float4* x1 = (const float4*)&sx[g * 4 + 1][0];
    const float4* x2 = (const float4*)&sx[g * 4 + 2][0];
    const float4* x3 = (const float4*)&sx[g * 4 + 3][0];

    float a0 = 0.f, a1 = 0.f, a2 = 0.f, a3 = 0.f;
#pragma unroll
    for (int kk = 0; kk < 32; kk++) {
        float4 w = wr[kk];
        a0 += dot4(x0[kk], w);
        a1 += dot4(x1[kk], w);
        a2 += dot4(x2[kk], w);
        a3 += dot4(x3[kk], w);
    }
    float bj = __ldg(b1 + j);
    float h0 = fmaxf(a0 + bj, 0.f);
    float h1 = fmaxf(a1 + bj, 0.f);
    float h2 = fmaxf(a2 + bj, 0.f);
    float h3 = fmaxf(a3 + bj, 0.f);

    // per-node inverse norm: reduce h^2 over the 16 j-lanes (half-warp)
    float s0 = h0 * h0, s1 = h1 * h1, s2 = h2 * h2, s3 = h3 * h3;
#pragma unroll
    for (int o = 1; o < 16; o <<= 1) {
        s0 += __shfl_xor_sync(0xffffffffu, s0, o);
        s1 += __shfl_xor_sync(0xffffffffu, s1, o);
        s2 += __shfl_xor_sync(0xffffffffu, s2, o);
        s3 += __shfl_xor_sync(0xffffffffu, s3, o);
    }

    int nd = base + g * 4;
    if (nd + 0 < n) g_bufA[(nd + 0) * ROWF + j] = h0;
    if (nd + 1 < n) g_bufA[(nd + 1) * ROWF + j] = h1;
    if (nd + 2 < n) g_bufA[(nd + 2) * ROWF + j] = h2;
    if (nd + 3 < n) g_bufA[(nd + 3) * ROWF + j] = h3;
    if (j == 0) {
        if (nd + 0 < n) g_rA[nd + 0] = (s0 > 1e-24f) ? rsqrtf(s0) : 1e12f;
        if (nd + 1 < n) g_rA[nd + 1] = (s1 > 1e-24f) ? rsqrtf(s1) : 1e12f;
        if (nd + 2 < n) g_rA[nd + 2] = (s2 > 1e-24f) ? rsqrtf(s2) : 1e12f;
        if (nd + 3 < n) g_rA[nd + 3] = (s3 > 1e-24f) ? rsqrtf(s3) : 1e12f;
    }
}

// ---------------- AGNN propagation (4 lanes/node, precomputed inv-norms) ----------------
template <bool FUSE_OUT>
__global__ void __launch_bounds__(256) k_prop(
    const float* __restrict__ xin, float* __restrict__ xout,
    const float* __restrict__ rin, float* __restrict__ rout,
    const float* __restrict__ beta_ptr, int n,
    const float* __restrict__ W2, const float* __restrict__ b2,
    float* __restrict__ out) {

    __shared__ float w2s[HID * NC];
    __shared__ float b2s[NC];
    __shared__ float sxs[64][20];

    int t = threadIdx.x;
    if (FUSE_OUT) {
        for (int idx = t; idx < HID * NC; idx += 256) w2s[idx] = W2[idx];
        if (t < NC) b2s[t] = b2[t];
    }

    int lane = t & 31;
    int sub = lane & 3;
    int gbase = lane & ~3;
    unsigned gm = 0xFu << gbase;
    int local = t >> 2;
    int node = blockIdx.x * 64 + local;
    bool act = node < n;
    int nn = act ? node : 0;

    float beta = beta_ptr ? __ldg(beta_ptr) : 1.0f;

    float4 d4 = ((const float4*)(xin + nn * ROWF))[sub];
    float n2d = dot4(d4, d4);
    n2d += __shfl_xor_sync(gm, n2d, 1);
    n2d += __shfl_xor_sync(gm, n2d, 2);
    float rd = __ldg(rin + nn);
    float c = beta * rd;

    int deg = act ? g_counts[nn] : 0;
    if (deg > CAP) deg = CAP;
    if (FUSE_OUT && act && sub == 0) g_counts[nn] = 0;  // reset for next replay
    const int* clist = g_csr + nn * CAP;

    float4 aA = make_float4(0.f, 0.f, 0.f, 0.f), aB = aA;
    float sA = 0.f, sB = 0.f;

    int2 sp = make_int2(0, 0);
    float2 rv = make_float2(0.f, 0.f);
    if (deg > 0) {
        sp = *(const int2*)(clist + 2 * sub);
        rv.x = __ldg(rin + sp.x);
        rv.y = __ldg(rin + sp.y);
    }

    for (int ch = 0; ch < deg; ch += 8) {
        int m = deg - ch;

        int j0 = __shfl_sync(gm, sp.x, gbase + 0);
        int j1 = __shfl_sync(gm, sp.y, gbase + 0);
        int j2 = __shfl_sync(gm, sp.x, gbase + 1);
        int j3 = __shfl_sync(gm, sp.y, gbase + 1);
        int j4 = __shfl_sync(gm, sp.x, gbase + 2);
        int j5 = __shfl_sync(gm, sp.y, gbase + 2);
        int j6 = __shfl_sync(gm, sp.x, gbase + 3);
        int j7 = __shfl_sync(gm, sp.y, gbase + 3);

        float c0 = c * __shfl_sync(gm, rv.x, gbase + 0);
        float c1 = c * __shfl_sync(gm, rv.y, gbase + 0);
        float c2 = c * __shfl_sync(gm, rv.x, gbase + 1);
        float c3 = c * __shfl_sync(gm, rv.y, gbase + 1);
        float c4 = c * __shfl_sync(gm, rv.x, gbase + 2);
        float c5 = c * __shfl_sync(gm, rv.y, gbase + 2);
        float c6 = c * __shfl_sync(gm, rv.x, gbase + 3);
        float c7 = c * __shfl_sync(gm, rv.y, gbase + 3);

        if (ch + 8 < deg) {
            sp = *(const int2*)(clist + ch + 8 + 2 * sub);
            rv.x = __ldg(rin + sp.x);
            rv.y = __ldg(rin + sp.y);
        }

        float4 q0 = ((const float4*)(xin + j0 * ROWF))[sub];
        float4 q1 = ((const float4*)(xin + j1 * ROWF))[sub];
        float4 q2 = ((const float4*)(xin + j2 * ROWF))[sub];
        float4 q3 = ((const float4*)(xin + j3 * ROWF))[sub];
        float4 q4 = ((const float4*)(xin + j4 * ROWF))[sub];
        float4 q5 = ((const float4*)(xin + j5 * ROWF))[sub];
        float4 q6 = ((const float4*)(xin + j6 * ROWF))[sub];
        float4 q7 = ((const float4*)(xin + j7 * ROWF))[sub];

#define PROC(Q, CRS, KK, SS, AA)                                          \
        {                                                                 \
            float pd = dot4(d4, Q);                                       \
            pd += __shfl_xor_sync(gm, pd, 1);                             \
            pd += __shfl_xor_sync(gm, pd, 2);                             \
            float w = (KK < m) ? __expf(CRS * pd) : 0.f;                  \
            SS += w;                                                      \
            AA.x = fmaf(w, Q.x, AA.x);                                    \
            AA.y = fmaf(w, Q.y, AA.y);                                    \
            AA.z = fmaf(w, Q.z, AA.z);                                    \
            AA.w = fmaf(w, Q.w, AA.w);                                    \
        }
        PROC(q0, c0, 0, sA, aA) PROC(q1, c1, 1, sB, aB)
        PROC(q2, c2, 2, sA, aA) PROC(q3, c3, 3, sB, aB)
        PROC(q4, c4, 4, sA, aA) PROC(q5, c5, 5, sB, aB)
        PROC(q6, c6, 6, sA, aA) PROC(q7, c7, 7, sB, aB)
#undef PROC
    }

    float s = sA + sB;
    float4 a4;
    a4.x = aA.x + aB.x; a4.y = aA.y + aB.y;
    a4.z = aA.z + aB.z; a4.w = aA.w + aB.w;

    float es = __expf(c * rd * n2d);      // self-loop: exp(beta*cos(x,x))
    float inv = 1.0f / (s + es);

    float4 o4;
    o4.x = (a4.x + es * d4.x) * inv;
    o4.y = (a4.y + es * d4.y) * inv;
    o4.z = (a4.z + es * d4.z) * inv;
    o4.w = (a4.w + es * d4.w) * inv;

    if (!FUSE_OUT) {
        float m2 = dot4(o4, o4);
        m2 += __shfl_xor_sync(gm, m2, 1);
        m2 += __shfl_xor_sync(gm, m2, 2);
        if (act) {
            ((float4*)(xout + node * ROWF))[sub] = o4;
            if (sub == 0) rout[node] = (m2 > 1e-24f) ? rsqrtf(m2) : 1e12f;
        }
        return;
    }

    // ---- fused 16->20 GEMM + log_softmax ----
    ((float4*)&sxs[local][0])[sub] = o4;
    __syncthreads();

    float xk[16];
#pragma unroll
    for (int k = 0; k < 16; k++) xk[k] = sxs[local][k];

    float o[5];
#pragma unroll
    for (int cc = 0; cc < 5; cc++) {
        int j = sub * 5 + cc;
        float acc = b2s[j];
#pragma unroll
        for (int k = 0; k < 16; k++) acc = fmaf(xk[k], w2s[k * NC + j], acc);
        o[cc] = acc;
    }
    float mx = o[0];
#pragma unroll
    for (int cc = 1; cc < 5; cc++) mx = fmaxf(mx, o[cc]);
    mx = fmaxf(mx, __shfl_xor_sync(gm, mx, 1));
    mx = fmaxf(mx, __shfl_xor_sync(gm, mx, 2));
    float se = 0.f;
#pragma unroll
    for (int cc = 0; cc < 5; cc++) se += __expf(o[cc] - mx);
    se += __shfl_xor_sync(gm, se, 1);
    se += __shfl_xor_sync(gm, se, 2);
    float lse = mx + logf(se);
    if (act) {
        float* orow = out + (size_t)node * NC + sub * 5;
#pragma unroll
        for (int cc = 0; cc < 5; cc++) orow[cc] = o[cc] - lse;
    }
}

// ---------------- launch ----------------
extern "C" void kernel_launch(void* const* d_in, const int* in_sizes, int n_in,
                              void* d_out, int out_size) {
    const int*   ids   = (const int*)d_in[0];
    const int*   eidx  = (const int*)d_in[1];
    const float* emb   = (const float*)d_in[2];
    const float* W1    = (const float*)d_in[3];
    const float* b1    = (const float*)d_in[4];
    const float* beta2 = (const float*)d_in[5];
    const float* W2    = (const float*)d_in[6];
    const float* b2    = (const float*)d_in[7];
    float* out = (float*)d_out;

    int n = in_sizes[0];
    int E = in_sizes[1] / 2;
    if (n > NN) n = NN;
    if (E > EE) E = EE;
    const int* src = eidx;
    const int* dst = eidx + E;

    float* bufA; cudaGetSymbolAddress((void**)&bufA, g_bufA);
    float* bufB; cudaGetSymbolAddress((void**)&bufB, g_bufB);
    float* rA;   cudaGetSymbolAddress((void**)&rA, g_rA);
    float* rB;   cudaGetSymbolAddress((void**)&rB, g_rB);

    int gemm_blks = (n + 63) / 64;                       // 1563
    int scat_blks = (E + 256 * 16 - 1) / (256 * 16);     // 782
    int trios = scat_blks > (gemm_blks + 1) / 2 ? scat_blks : (gemm_blks + 1) / 2;
    k_front<<<trios * 3, 256>>>(ids, emb, W1, b1, src, dst, n, E, trios, gemm_blks);
    k_prop<false><<<(n + 63) / 64, 256>>>(bufA, bufB, rA, rB, nullptr, n, nullptr, nullptr, nullptr);
    k_prop<true><<<(n + 63) / 64, 256>>>(bufB, nullptr, rB, nullptr, beta2, n, W2, b2, out);
}

// round 9
// speedup vs baseline: 1.0758x; 1.0758x over previous
#include <cuda_runtime.h>
#include <math.h>

#define NN 100000
#define EE 3200000
#define FEAT 128
#define HID 16
#define NC 20
#define CAP 128            // padded CSR slots per node
#define ROWF 16            // 64B row

// ---- device scratch ----
__device__ __align__(128) float g_bufA[NN * ROWF];
__device__ __align__(128) float g_bufB[NN * ROWF];
__device__ int   g_counts[NN];        // BSS-zeroed; re-zeroed by prop2 each launch
__device__ int   g_csr[NN * CAP + 64];  // +64 pad: unconditional int2 prefetch safety

__device__ __forceinline__ float dot4(float4 a, float4 b) {
    return a.x * b.x + a.y * b.y + a.z * b.z + a.w * b.w;
}

// ---------------- fused front: interleaved CSR-scatter + gemm1 blocks (R7) ----------------
// bid % 3 == 0 -> gemm block (gemm_id = bid/3, 64 nodes each, 4 nodes/thread)
// else         -> scatter block (scat_id = (bid/3)*2 + rem-1)
__global__ void __launch_bounds__(256) k_front(
    const int* __restrict__ ids, const float* __restrict__ emb,
    const float* __restrict__ W1, const float* __restrict__ b1,
    const int* __restrict__ src, const int* __restrict__ dst,
    int n, int E, int nscat) {

    int bid = blockIdx.x;
    int rem = bid % 3;

    if (rem != 0) {
        // ---- scatter: 8 edges / iteration, MLP-8 atomics ----
        int scat_id = (bid / 3) * 2 + (rem - 1);
        int tid = scat_id * 256 + threadIdx.x;
        int stride = nscat * 256;
        const int4* src4 = (const int4*)src;
        const int4* dst4 = (const int4*)dst;
        int E8 = E >> 3;
        for (int i = tid; i < E8; i += stride) {
            int4 d0 = __ldg(dst4 + 2 * i);
            int4 d1 = __ldg(dst4 + 2 * i + 1);
            int4 s0 = __ldg(src4 + 2 * i);
            int4 s1 = __ldg(src4 + 2 * i + 1);
            int p0 = atomicAdd(&g_counts[d0.x], 1);
            int p1 = atomicAdd(&g_counts[d0.y], 1);
            int p2 = atomicAdd(&g_counts[d0.z], 1);
            int p3 = atomicAdd(&g_counts[d0.w], 1);
            int p4 = atomicAdd(&g_counts[d1.x], 1);
            int p5 = atomicAdd(&g_counts[d1.y], 1);
            int p6 = atomicAdd(&g_counts[d1.z], 1);
            int p7 = atomicAdd(&g_counts[d1.w], 1);
            if (p0 < CAP) g_csr[d0.x * CAP + p0] = s0.x;
            if (p1 < CAP) g_csr[d0.y * CAP + p1] = s0.y;
            if (p2 < CAP) g_csr[d0.z * CAP + p2] = s0.z;
            if (p3 < CAP) g_csr[d0.w * CAP + p3] = s0.w;
            if (p4 < CAP) g_csr[d1.x * CAP + p4] = s1.x;
            if (p5 < CAP) g_csr[d1.y * CAP + p5] = s1.y;
            if (p6 < CAP) g_csr[d1.z * CAP + p6] = s1.z;
            if (p7 < CAP) g_csr[d1.w * CAP + p7] = s1.w;
        }
        for (int i = (E8 << 3) + tid; i < E; i += stride) {
            int d = __ldg(dst + i);
            int p = atomicAdd(&g_counts[d], 1);
            if (p < CAP) g_csr[d * CAP + p] = __ldg(src + i);
        }
        return;
    }

    // ---- gemm1: 64 nodes/block, 4 nodes/thread (W reused 4x from regs) ----
    __shared__ float w1t[16 * 132];      // W1^T
    __shared__ float sx[64][132];        // 64 staged emb rows

    int t = threadIdx.x;
    for (int idx = t; idx < FEAT * HID; idx += 256) {
        int k = idx >> 4, j = idx & 15;
        w1t[j * 132 + k] = W1[idx];
    }

    int base = (bid / 3) * 64;
    int warp = t >> 5, lane = t & 31;

    for (int rr = warp; rr < 64; rr += 8) {
        int node = base + rr;
        int id = (node < n) ? __ldg(ids + node) : 0;
        float4 v = __ldg(((const float4*)(emb + (size_t)id * FEAT)) + lane);
        ((float4*)&sx[rr][0])[lane] = v;
    }
    __syncthreads();

    int j = t & 15, g = t >> 4;          // 16 groups x 4 nodes
    const float4* wr = (const float4*)(w1t + j * 132);
    const float4* x0 = (const float4*)&sx[g * 4 + 0][0];
    const float4* x1 = (const float4*)&sx[g * 4 + 1][0];
    const float4* x2 = (const float4*)&sx[g * 4 + 2][0];
    const float4* x3 = (const float4*)&sx[g * 4 + 3][0];

    float a0 = 0.f, a1 = 0.f, a2 = 0.f, a3 = 0.f;
#pragma unroll
    for (int kk = 0; kk < 32; kk++) {
        float4 w = wr[kk];
        a0 += dot4(x0[kk], w);
        a1 += dot4(x1[kk], w);
        a2 += dot4(x2[kk], w);
        a3 += dot4(x3[kk], w);
    }
    float bj = __ldg(b1 + j);
    int nd = base + g * 4;
    if (nd + 0 < n) g_bufA[(nd + 0) * ROWF + j] = fmaxf(a0 + bj, 0.f);
    if (nd + 1 < n) g_bufA[(nd + 1) * ROWF + j] = fmaxf(a1 + bj, 0.f);
    if (nd + 2 < n) g_bufA[(nd + 2) * ROWF + j] = fmaxf(a2 + bj, 0.f);
    if (nd + 3 < n) g_bufA[(nd + 3) * ROWF + j] = fmaxf(a3 + bj, 0.f);
}

// ---------------- AGNN propagation (4 lanes/node, full chunks unconditional + tail) ----------------
template <bool FUSE_OUT>
__global__ void __launch_bounds__(256) k_prop(
    const float* __restrict__ xin, float* __restrict__ xout,
    const float* __restrict__ beta_ptr, int n,
    const float* __restrict__ W2, const float* __restrict__ b2,
    float* __restrict__ out) {

    __shared__ float w2s[HID * NC];
    __shared__ float b2s[NC];
    __shared__ float sxs[64][20];

    int t = threadIdx.x;
    if (FUSE_OUT) {
        for (int idx = t; idx < HID * NC; idx += 256) w2s[idx] = W2[idx];
        if (t < NC) b2s[t] = b2[t];
    }

    int lane = t & 31;
    int sub = lane & 3;
    int gbase = lane & ~3;
    unsigned gm = 0xFu << gbase;
    int local = t >> 2;
    int node = blockIdx.x * 64 + local;
    bool act = node < n;
    int nn = act ? node : 0;

    float beta = beta_ptr ? __ldg(beta_ptr) : 1.0f;

    float4 d4 = ((const float4*)(xin + nn * ROWF))[sub];
    float n2d = dot4(d4, d4);
    n2d += __shfl_xor_sync(gm, n2d, 1);
    n2d += __shfl_xor_sync(gm, n2d, 2);
    float rd = (n2d > 1e-24f) ? rsqrtf(n2d) : 1e12f;
    float c = beta * rd;

    int deg = act ? g_counts[nn] : 0;
    if (deg > CAP) deg = CAP;
    if (FUSE_OUT && act && sub == 0) g_counts[nn] = 0;  // reset for next replay
    const int* clist = g_csr + nn * CAP;

    float4 aA = make_float4(0.f, 0.f, 0.f, 0.f), aB = aA;
    float sA = 0.f, sB = 0.f;

    int2 sp = (deg > 0) ? *(const int2*)(clist + 2 * sub) : make_int2(0, 0);
    int full = deg & ~7;

#define LOADQ                                                              \
        int j0 = __shfl_sync(gm, sp.x, gbase + 0);                         \
        int j1 = __shfl_sync(gm, sp.y, gbase + 0);                         \
        int j2 = __shfl_sync(gm, sp.x, gbase + 1);                         \
        int j3 = __shfl_sync(gm, sp.y, gbase + 1);                         \
        int j4 = __shfl_sync(gm, sp.x, gbase + 2);                         \
        int j5 = __shfl_sync(gm, sp.y, gbase + 2);                         \
        int j6 = __shfl_sync(gm, sp.x, gbase + 3);                         \
        int j7 = __shfl_sync(gm, sp.y, gbase + 3);                         \
        float4 q0 = ((const float4*)(xin + j0 * ROWF))[sub];               \
        float4 q1 = ((const float4*)(xin + j1 * ROWF))[sub];               \
        float4 q2 = ((const float4*)(xin + j2 * ROWF))[sub];               \
        float4 q3 = ((const float4*)(xin + j3 * ROWF))[sub];               \
        float4 q4 = ((const float4*)(xin + j4 * ROWF))[sub];               \
        float4 q5 = ((const float4*)(xin + j5 * ROWF))[sub];               \
        float4 q6 = ((const float4*)(xin + j6 * ROWF))[sub];               \
        float4 q7 = ((const float4*)(xin + j7 * ROWF))[sub];

#define PROCU(Q, SS, AA)                                                   \
        {                                                                  \
            float pd = dot4(d4, Q);                                        \
            float qq = dot4(Q, Q);                                         \
            pd += __shfl_xor_sync(gm, pd, 1);                              \
            qq += __shfl_xor_sync(gm, qq, 1);                              \
            pd += __shfl_xor_sync(gm, pd, 2);                              \
            qq += __shfl_xor_sync(gm, qq, 2);                              \
            float rs = (qq > 1e-24f) ? rsqrtf(qq) : 1e12f;                 \
            float w = __expf(c * rs * pd);                                 \
            SS += w;                                                       \
            AA.x = fmaf(w, Q.x, AA.x);                                     \
            AA.y = fmaf(w, Q.y, AA.y);                                     \
            AA.z = fmaf(w, Q.z, AA.z);                                     \
            AA.w = fmaf(w, Q.w, AA.w);                                     \
        }

#define PROCM(Q, KK, SS, AA)                                               \
        {                                                                  \
            float pd = dot4(d4, Q);                                        \
            float qq = dot4(Q, Q);                                         \
            pd += __shfl_xor_sync(gm, pd, 1);                              \
            qq += __shfl_xor_sync(gm, qq, 1);                              \
            pd += __shfl_xor_sync(gm, pd, 2);                              \
            qq += __shfl_xor_sync(gm, qq, 2);                              \
            float rs = (qq > 1e-24f) ? rsqrtf(qq) : 1e12f;                 \
            float w = (KK < m) ? __expf(c * rs * pd) : 0.f;                \
            SS += w;                                                       \
            AA.x = fmaf(w, Q.x, AA.x);                                     \
            AA.y = fmaf(w, Q.y, AA.y);                                     \
            AA.z = fmaf(w, Q.z, AA.z);                                     \
            AA.w = fmaf(w, Q.w, AA.w);                                     \
        }

    // full 8-edge chunks: no per-edge masking
    for (int ch = 0; ch < full; ch += 8) {
        LOADQ
        sp = *(const int2*)(clist + ch + 8 + 2 * sub);   // padded array: always safe
        PROCU(q0, sA, aA) PROCU(q1, sB, aB)
        PROCU(q2, sA, aA) PROCU(q3, sB, aB)
        PROCU(q4, sA, aA) PROCU(q5, sB, aB)
        PROCU(q6, sA, aA) PROCU(q7, sB, aB)
    }
    // tail chunk (1..7 edges), masked
    if (full < deg) {
        int m = deg - full;
        LOADQ
        PROCM(q0, 0, sA, aA) PROCM(q1, 1, sB, aB)
        PROCM(q2, 2, sA, aA) PROCM(q3, 3, sB, aB)
        PROCM(q4, 4, sA, aA) PROCM(q5, 5, sB, aB)
        PROCM(q6, 6, sA, aA) PROCM(q7, 7, sB, aB)
    }
#undef LOADQ
#undef PROCU
#undef PROCM

    float s = sA + sB;
    float4 a4;
    a4.x = aA.x + aB.x; a4.y = aA.y + aB.y;
    a4.z = aA.z + aB.z; a4.w = aA.w + aB.w;

    float es = __expf(c * rd * n2d);      // self-loop: exp(beta*cos(x,x))
    float inv = 1.0f / (s + es);

    float4 o4;
    o4.x = (a4.x + es * d4.x) * inv;
    o4.y = (a4.y + es * d4.y) * inv;
    o4.z = (a4.z + es * d4.z) * inv;
    o4.w = (a4.w + es * d4.w) * inv;

    if (!FUSE_OUT) {
        if (act) ((float4*)(xout + node * ROWF))[sub] = o4;
        return;
    }

    // ---- fused 16->20 GEMM + log_softmax ----
    ((float4*)&sxs[local][0])[sub] = o4;
    __syncthreads();

    float xk[16];
#pragma unroll
    for (int k = 0; k < 16; k++) xk[k] = sxs[local][k];

    float o[5];
#pragma unroll
    for (int cc = 0; cc < 5; cc++) {
        int j = sub * 5 + cc;
        float acc = b2s[j];
#pragma unroll
        for (int k = 0; k < 16; k++) acc = fmaf(xk[k], w2s[k * NC + j], acc);
        o[cc] = acc;
    }
    float mx = o[0];
#pragma unroll
    for (int cc = 1; cc < 5; cc++) mx = fmaxf(mx, o[cc]);
    mx = fmaxf(mx, __shfl_xor_sync(gm, mx, 1));
    mx = fmaxf(mx, __shfl_xor_sync(gm, mx, 2));
    float se = 0.f;
#pragma unroll
    for (int cc = 0; cc < 5; cc++) se += __expf(o[cc] - mx);
    se += __shfl_xor_sync(gm, se, 1);
    se += __shfl_xor_sync(gm, se, 2);
    float lse = mx + logf(se);
    if (act) {
        float* orow = out + (size_t)node * NC + sub * 5;
#pragma unroll
        for (int cc = 0; cc < 5; cc++) orow[cc] = o[cc] - lse;
    }
}

// ---------------- launch ----------------
extern "C" void kernel_launch(void* const* d_in, const int* in_sizes, int n_in,
                              void* d_out, int out_size) {
    const int*   ids   = (const int*)d_in[0];
    const int*   eidx  = (const int*)d_in[1];
    const float* emb   = (const float*)d_in[2];
    const float* W1    = (const float*)d_in[3];
    const float* b1    = (const float*)d_in[4];
    const float* beta2 = (const float*)d_in[5];
    const float* W2    = (const float*)d_in[6];
    const float* b2    = (const float*)d_in[7];
    float* out = (float*)d_out;

    int n = in_sizes[0];
    int E = in_sizes[1] / 2;
    if (n > NN) n = NN;
    if (E > EE) E = EE;
    const int* src = eidx;
    const int* dst = eidx + E;

    float* bufA; cudaGetSymbolAddress((void**)&bufA, g_bufA);
    float* bufB; cudaGetSymbolAddress((void**)&bufB, g_bufB);

    int gemm_blks = (n + 63) / 64;        // 1563
    int nscat = gemm_blks * 2;            // 2 scatter blocks per gemm block (R7 layout)
    int total = gemm_blks * 3;
    k_front<<<total, 256>>>(ids, emb, W1, b1, src, dst, n, E, nscat);
    k_prop<false><<<(n + 63) / 64, 256>>>(bufA, bufB, nullptr, n, nullptr, nullptr, nullptr);
    k_prop<true><<<(n + 63) / 64, 256>>>(bufB, nullptr, beta2, n, W2, b2, out);
}